// round 13
// baseline (speedup 1.0000x reference)
#include <cuda_runtime.h>
#include <cuda_fp16.h>
#include <cstdint>

// ============================================================================
// relu(x @ W^T + b):  B=131072, D_IN=D_OUT=256, fp32 in/out.
//
// R13 vs R12 (101.1us, phase-serialization bound: 1 CTA/SM, barriers gang all
// 16 warps; prologue+epilogue exposed at every CTA wave):
//   - CTA tile 128x128, 256 threads / 8 warps (2Mx4N, warp tile 64x32 kept),
//     __launch_bounds__(256,2) -> TWO independent CTAs per SM. Same warps/SM,
//     same per-output LDS volume, but independent barriers/phases: one CTA's
//     compute hides the other's loads, prologue and epilogue.
//   - Grid (2, 1024), N-split fastest: the x-sharing sibling pair co-runs,
//     second x read served by L2.
//   - Everything else verbatim from R12: m16n8k16 fp16 HMMA (fp32 accum,
//     cvt.rn operands, rel_err 2.77e-4 measured), XOR word swizzle, 2-stage
//     ring + one-chunk-ahead register prefetch. Static 33KB smem.
// ============================================================================

#define DEVINL static __device__ __forceinline__

static constexpr int DIM     = 256;
static constexpr int TILE_M  = 128;
static constexpr int TILE_N  = 128;
static constexpr int NCH     = 8;                  // K chunks of 32
static constexpr int THREADS = 256;
static constexpr int ROW_H   = 32;                 // halfs per row-chunk (64 B)

static constexpr int A_HALFS     = TILE_M * ROW_H;        // 4096
static constexpr int B_HALFS     = TILE_N * ROW_H;        // 4096
static constexpr int STAGE_HALFS = A_HALFS + B_HALFS;     // 8192 (16 KB)

DEVINL uint32_t pack_h2(float lo, float hi) {       // f16x2 {lo | hi<<16}
    uint32_t r;
    asm("cvt.rn.f16x2.f32 %0, %1, %2;" : "=r"(r) : "f"(hi), "f"(lo));
    return r;
}

DEVINL void mma_f16(float* d, const uint32_t* a, const uint32_t* b) {
    asm volatile(
        "mma.sync.aligned.m16n8k16.row.col.f32.f16.f16.f32 "
        "{%0,%1,%2,%3}, {%4,%5,%6,%7}, {%8,%9}, {%0,%1,%2,%3};"
        : "+f"(d[0]), "+f"(d[1]), "+f"(d[2]), "+f"(d[3])
        : "r"(a[0]), "r"(a[1]), "r"(a[2]), "r"(a[3]),
          "r"(b[0]), "r"(b[1]));
}

__global__ void __launch_bounds__(THREADS, 2)
gemm_bias_relu_f16(const float4* __restrict__ x4,
                   const float4* __restrict__ w4,
                   const float*  __restrict__ bias,
                   float2*       __restrict__ out2) {
    __shared__ float  bsm[TILE_N];
    __shared__ __half stgbuf[2][STAGE_HALFS];

    const int  tid    = threadIdx.x;
    const int  n_base = blockIdx.x * TILE_N;        // 0 or 128 (fastest dim)
    const long m_base = (long)blockIdx.y * TILE_M;

    if (tid < TILE_N) bsm[tid] = bias[n_base + tid];

    // ---------------- loader mapping (256 threads) ----------------
    // Thread owns A rows {row, row+64} and W rows {row, row+64}; 16B seg s.
    // XOR swizzle: 16B slot sw = s ^ ((row>>1)&3)  (row and row+64 agree).
    const int row = tid >> 2;                      // 0..63
    const int s   = tid & 3;                       // 0..3
    const int sw  = s ^ ((row >> 1) & 3);

    const int soA0 = row * ROW_H + 8 * sw;
    const int soA1 = (row + 64) * ROW_H + 8 * sw;
    const int soB0 = A_HALFS + row * ROW_H + 8 * sw;
    const int soB1 = A_HALFS + (row + 64) * ROW_H + 8 * sw;

    const long gaA0 = (m_base + row) * 64 + s * 2;            // float4 units
    const long gaA1 = (m_base + row + 64) * 64 + s * 2;
    const long gaB0 = ((long)n_base + row) * 64 + s * 2;
    const long gaB1 = ((long)n_base + row + 64) * 64 + s * 2;

    float4 ra0[2], ra1[2], rb0[2], rb1[2];

    auto ldg_chunk = [&](int c) {
        const long o = (long)c * 8;
        ra0[0] = x4[gaA0 + o];   ra0[1] = x4[gaA0 + o + 1];
        ra1[0] = x4[gaA1 + o];   ra1[1] = x4[gaA1 + o + 1];
        rb0[0] = w4[gaB0 + o];   rb0[1] = w4[gaB0 + o + 1];
        rb1[0] = w4[gaB1 + o];   rb1[1] = w4[gaB1 + o + 1];
    };

    auto pack16 = [](const float4* v) {
        uint4 u;
        u.x = pack_h2(v[0].x, v[0].y);
        u.y = pack_h2(v[0].z, v[0].w);
        u.z = pack_h2(v[1].x, v[1].y);
        u.w = pack_h2(v[1].z, v[1].w);
        return u;
    };

    auto sts_chunk = [&](__half* st) {
        *(uint4*)(st + soA0) = pack16(ra0);
        *(uint4*)(st + soA1) = pack16(ra1);
        *(uint4*)(st + soB0) = pack16(rb0);
        *(uint4*)(st + soB1) = pack16(rb1);
    };

    // ---------------- compute mapping: 8 warps, 2(M) x 4(N) ----------------
    const int wid = tid >> 5, l = tid & 31;
    const int mw = wid >> 2, nw = wid & 3;
    const int qr = l >> 2, ql = l & 3;
    const int xq = (qr >> 1) & 3;

    // fragment group u=0..3 (u = 2*ks + {k, k+8}): phys half-off = 2*(ql+4*(u^xq))
    int woff[4];
#pragma unroll
    for (int u = 0; u < 4; u++) woff[u] = (ql + 4 * (u ^ xq)) * 2;

    int arow[4], brow[4];
#pragma unroll
    for (int mi = 0; mi < 4; mi++)
        arow[mi] = (mw * 64 + mi * 16 + qr) * ROW_H;
#pragma unroll
    for (int ni = 0; ni < 4; ni++)
        brow[ni] = A_HALFS + (nw * 32 + ni * 8 + qr) * ROW_H;

    float acc[4][4][4];
#pragma unroll
    for (int mi = 0; mi < 4; mi++)
#pragma unroll
        for (int ni = 0; ni < 4; ni++)
#pragma unroll
            for (int r = 0; r < 4; r++) acc[mi][ni][r] = 0.0f;

    auto ld32 = [](const __half* p) { return *(const uint32_t*)p; };

    auto compute_chunk = [&](const __half* st) {
#pragma unroll
        for (int ks = 0; ks < 2; ks++) {           // K=16 per mma
            const int u0 = woff[2 * ks], u1 = woff[2 * ks + 1];
            uint32_t a[4][4], b[4][2];
#pragma unroll
            for (int mi = 0; mi < 4; mi++) {
                const __half* p = st + arow[mi];
                a[mi][0] = ld32(p + u0);
                a[mi][1] = ld32(p + 8 * ROW_H + u0);
                a[mi][2] = ld32(p + u1);
                a[mi][3] = ld32(p + 8 * ROW_H + u1);
            }
#pragma unroll
            for (int ni = 0; ni < 4; ni++) {
                const __half* p = st + brow[ni];
                b[ni][0] = ld32(p + u0);
                b[ni][1] = ld32(p + u1);
            }
#pragma unroll
            for (int mi = 0; mi < 4; mi++)
#pragma unroll
                for (int ni = 0; ni < 4; ni++)
                    mma_f16(acc[mi][ni], a[mi], b[ni]);
        }
    };

    // ---------------- pipeline ----------------
    ldg_chunk(0);
    sts_chunk(stgbuf[0]);
    ldg_chunk(1);
    __syncthreads();

#pragma unroll 1
    for (int c = 0; c < NCH; c++) {
        compute_chunk(stgbuf[c & 1]);
        if (c < NCH - 1) {
            sts_chunk(stgbuf[(c + 1) & 1]);        // regs hold chunk c+1
            if (c < NCH - 2) ldg_chunk(c + 2);     // hidden by compute(c+1)
        }
        __syncthreads();
    }

    // ---------------- epilogue: bias + relu, float2 stores ----------------
#pragma unroll
    for (int mi = 0; mi < 4; mi++) {
        const long r0 = m_base + mw * 64 + mi * 16 + qr;
#pragma unroll
        for (int ni = 0; ni < 4; ni++) {
            const int col = nw * 32 + ni * 8 + ql * 2;     // local col
            const float b0 = bsm[col], b1 = bsm[col + 1];
            float2 v0, v1;
            v0.x = fmaxf(acc[mi][ni][0] + b0, 0.0f);
            v0.y = fmaxf(acc[mi][ni][1] + b1, 0.0f);
            v1.x = fmaxf(acc[mi][ni][2] + b0, 0.0f);
            v1.y = fmaxf(acc[mi][ni][3] + b1, 0.0f);
            const int gc2 = (n_base + col) >> 1;           // float2 col index
            out2[r0 * 128 + gc2]       = v0;
            out2[(r0 + 8) * 128 + gc2] = v1;
        }
    }
}

extern "C" void kernel_launch(void* const* d_in, const int* in_sizes, int n_in,
                              void* d_out, int out_size) {
    const float* x = (const float*)d_in[0];   // [B, 256]
    const float* W = (const float*)d_in[1];   // [256, 256]
    const float* b = (const float*)d_in[2];   // [256]

    const int rows = in_sizes[0] / DIM;       // 131072
    dim3 grid(DIM / TILE_N, rows / TILE_M);   // (2, 1024), N fastest

    gemm_bias_relu_f16<<<grid, THREADS>>>(
        (const float4*)x, (const float4*)W, b, (float2*)d_out);
}

// round 15
// speedup vs baseline: 1.5508x; 1.5508x over previous
#include <cuda_runtime.h>
#include <cuda_fp16.h>
#include <cstdint>

// ============================================================================
// relu(x @ W^T + b):  B=131072, D_IN=D_OUT=256, fp32 in/out.
//
// R14 vs R12 (101.1us, L1TEX-work bound ~11.8k wavefronts/CTA):
//  1) 64x64 warp tiles: 8 warps / 256 threads (2Mx4N over CTA 128x256).
//     Fragment LDS volume -33% (6144 -> 4096 wf/CTA).
//  2) W pre-converted to fp16 once into a __device__ buffer by a tiny
//     pre-kernel: main-loop W LDG halves (fp16 16B units, no cvt/pack).
//  Kept verbatim: m16n8k16 fp16 HMMA + fp32 accum (rel_err 2.77e-4 measured),
//  XOR word swizzle (conflict-free LDS/STS), 2-stage ring + one-chunk-ahead
//  register prefetch, grid 1024 (no N split -- R13 falsified that).
// ============================================================================

#define DEVINL static __device__ __forceinline__

static constexpr int DIM     = 256;
static constexpr int TILE_M  = 128;
static constexpr int NCH     = 8;                  // K chunks of 32
static constexpr int THREADS = 256;
static constexpr int ROW_H   = 32;                 // halfs per row-chunk (64 B)

static constexpr int A_HALFS     = TILE_M * ROW_H;        // 4096
static constexpr int B_HALFS     = DIM * ROW_H;           // 8192
static constexpr int STAGE_HALFS = A_HALFS + B_HALFS;     // 12288 (24 KB)
static constexpr int BIAS_WORDS  = 256;
static constexpr int SMEM_BYTES  = BIAS_WORDS * 4 + 2 * STAGE_HALFS * 2; // 50176

__device__ __half2 g_Wh[DIM * DIM / 2];            // W in fp16, row-major [N][K]

__global__ void __launch_bounds__(256, 4)
convert_W_f16(const float2* __restrict__ w2) {
    const int i = blockIdx.x * 256 + threadIdx.x;  // 32768 float2
    const float2 v = w2[i];
    g_Wh[i] = __floats2half2_rn(v.x, v.y);         // RN, matches cvt.rn.f16x2
}

DEVINL uint32_t pack_h2(float lo, float hi) {      // f16x2 {lo | hi<<16}
    uint32_t r;
    asm("cvt.rn.f16x2.f32 %0, %1, %2;" : "=r"(r) : "f"(hi), "f"(lo));
    return r;
}

DEVINL void mma_f16(float* d, const uint32_t* a, const uint32_t* b) {
    asm volatile(
        "mma.sync.aligned.m16n8k16.row.col.f32.f16.f16.f32 "
        "{%0,%1,%2,%3}, {%4,%5,%6,%7}, {%8,%9}, {%0,%1,%2,%3};"
        : "+f"(d[0]), "+f"(d[1]), "+f"(d[2]), "+f"(d[3])
        : "r"(a[0]), "r"(a[1]), "r"(a[2]), "r"(a[3]),
          "r"(b[0]), "r"(b[1]));
}

__global__ void __launch_bounds__(THREADS, 1)
gemm_bias_relu_f16(const float4* __restrict__ x4,
                   const float*  __restrict__ bias,
                   float2*       __restrict__ out2) {
    extern __shared__ float smf[];
    float*  bsm = smf;
    __half* hb  = (__half*)(smf + BIAS_WORDS);
    __half* stg[2] = { hb, hb + STAGE_HALFS };

    const int  tid    = threadIdx.x;
    const long m_base = (long)blockIdx.x * TILE_M;
    const uint4* wh4  = (const uint4*)g_Wh;        // 16B = 8 halfs

    bsm[tid] = bias[tid];

    // ---------------- loader mapping (256 threads) ----------------
    // row = tid>>2 (0..63), s = 16B k-segment (0..3).
    // A rows {row, row+64} from fp32 x (2 float4 -> pack to 16B fp16).
    // B rows {row+64j, j=0..3} from fp16 g_Wh (straight 16B copy).
    // XOR swizzle slot: sw = s ^ ((row>>1)&3)  (invariant under row+64k).
    const int row = tid >> 2;
    const int s   = tid & 3;
    const int sw  = s ^ ((row >> 1) & 3);

    long gaA[2];  int soA[2];
#pragma unroll
    for (int i = 0; i < 2; i++) {
        gaA[i] = (m_base + row + 64 * i) * 64 + s * 2;       // float4 units
        soA[i] = (row + 64 * i) * ROW_H + 8 * sw;
    }
    int gbB[4], soB[4];
#pragma unroll
    for (int j = 0; j < 4; j++) {
        gbB[j] = (row + 64 * j) * 32 + s;                    // uint4 units, +c*4
        soB[j] = A_HALFS + (row + 64 * j) * ROW_H + 8 * sw;
    }

    float4 ra[2][2];
    uint4  rb[4];

    auto ldg_chunk = [&](int c) {
        const long o = (long)c * 8;
#pragma unroll
        for (int i = 0; i < 2; i++) {
            ra[i][0] = x4[gaA[i] + o];
            ra[i][1] = x4[gaA[i] + o + 1];
        }
#pragma unroll
        for (int j = 0; j < 4; j++) rb[j] = wh4[gbB[j] + c * 4];
    };

    auto pack16 = [](const float4* v) {
        uint4 u;
        u.x = pack_h2(v[0].x, v[0].y);
        u.y = pack_h2(v[0].z, v[0].w);
        u.z = pack_h2(v[1].x, v[1].y);
        u.w = pack_h2(v[1].z, v[1].w);
        return u;
    };

    auto sts_chunk = [&](__half* st) {
#pragma unroll
        for (int i = 0; i < 2; i++) *(uint4*)(st + soA[i]) = pack16(ra[i]);
#pragma unroll
        for (int j = 0; j < 4; j++) *(uint4*)(st + soB[j]) = rb[j];
    };

    // ---------------- compute mapping: 8 warps, 2(M) x 4(N), 64x64 ----------
    const int wid = tid >> 5, l = tid & 31;
    const int mw = wid >> 2, nw = wid & 3;
    const int qr = l >> 2, ql = l & 3;
    const int xq = (qr >> 1) & 3;

    int woff[4];                                    // phys half-off per frag group
#pragma unroll
    for (int u = 0; u < 4; u++) woff[u] = (ql + 4 * (u ^ xq)) * 2;

    int arow[4], brow[8];
#pragma unroll
    for (int mi = 0; mi < 4; mi++)
        arow[mi] = (mw * 64 + mi * 16 + qr) * ROW_H;
#pragma unroll
    for (int ni = 0; ni < 8; ni++)
        brow[ni] = A_HALFS + (nw * 64 + ni * 8 + qr) * ROW_H;

    float acc[4][8][4];
#pragma unroll
    for (int mi = 0; mi < 4; mi++)
#pragma unroll
        for (int ni = 0; ni < 8; ni++)
#pragma unroll
            for (int r = 0; r < 4; r++) acc[mi][ni][r] = 0.0f;

    auto ld32 = [](const __half* p) { return *(const uint32_t*)p; };

    auto compute_chunk = [&](const __half* st) {
#pragma unroll
        for (int ks = 0; ks < 2; ks++) {           // K=16 per mma
            const int u0 = woff[2 * ks], u1 = woff[2 * ks + 1];
            uint32_t a[4][4], b[8][2];
#pragma unroll
            for (int mi = 0; mi < 4; mi++) {
                const __half* p = st + arow[mi];
                a[mi][0] = ld32(p + u0);
                a[mi][1] = ld32(p + 8 * ROW_H + u0);
                a[mi][2] = ld32(p + u1);
                a[mi][3] = ld32(p + 8 * ROW_H + u1);
            }
#pragma unroll
            for (int ni = 0; ni < 8; ni++) {
                const __half* p = st + brow[ni];
                b[ni][0] = ld32(p + u0);
                b[ni][1] = ld32(p + u1);
            }
#pragma unroll
            for (int mi = 0; mi < 4; mi++)
#pragma unroll
                for (int ni = 0; ni < 8; ni++)
                    mma_f16(acc[mi][ni], a[mi], b[ni]);
        }
    };

    // ---------------- pipeline ----------------
    ldg_chunk(0);
    sts_chunk(stg[0]);
    ldg_chunk(1);
    __syncthreads();

#pragma unroll 1
    for (int c = 0; c < NCH; c++) {
        compute_chunk(stg[c & 1]);
        if (c < NCH - 1) {
            sts_chunk(stg[(c + 1) & 1]);           // regs hold chunk c+1
            if (c < NCH - 2) ldg_chunk(c + 2);     // hidden by compute(c+1)
        }
        __syncthreads();
    }

    // ---------------- epilogue: bias + relu, float2 stores ----------------
#pragma unroll
    for (int mi = 0; mi < 4; mi++) {
        const long r0 = m_base + mw * 64 + mi * 16 + qr;
#pragma unroll
        for (int ni = 0; ni < 8; ni++) {
            const int col = nw * 64 + ni * 8 + ql * 2;
            const float b0 = bsm[col], b1 = bsm[col + 1];
            float2 v0, v1;
            v0.x = fmaxf(acc[mi][ni][0] + b0, 0.0f);
            v0.y = fmaxf(acc[mi][ni][1] + b1, 0.0f);
            v1.x = fmaxf(acc[mi][ni][2] + b0, 0.0f);
            v1.y = fmaxf(acc[mi][ni][3] + b1, 0.0f);
            out2[r0 * 128 + (col >> 1)]       = v0;
            out2[(r0 + 8) * 128 + (col >> 1)] = v1;
        }
    }
}

extern "C" void kernel_launch(void* const* d_in, const int* in_sizes, int n_in,
                              void* d_out, int out_size) {
    const float* x = (const float*)d_in[0];   // [B, 256]
    const float* W = (const float*)d_in[1];   // [256, 256]
    const float* b = (const float*)d_in[2];   // [256]

    const int rows = in_sizes[0] / DIM;       // 131072
    const int grid = rows / TILE_M;           // 1024

    convert_W_f16<<<DIM * DIM / 2 / 256, 256>>>((const float2*)W);

    cudaFuncSetAttribute(gemm_bias_relu_f16,
                         cudaFuncAttributeMaxDynamicSharedMemorySize, SMEM_BYTES);
    gemm_bias_relu_f16<<<grid, THREADS, SMEM_BYTES>>>(
        (const float4*)x, b, (float2*)d_out);
}